// round 9
// baseline (speedup 1.0000x reference)
#include <cuda_runtime.h>
#include <cuda_fp16.h>
#include <cstdint>

// Problem constants (fixed by the dataset)
#define BATCH 2
#define SEQ   512
#define BS    (BATCH * SEQ)      // 1024 tokens
#define FDIM  16384              // n_features
#define DDIM  768                // d_model
#define MCON  262144             // n_connections

// SpMM tile
#define TI 32    // i rows per block
#define TT 256   // tokens per block (lane owns 8 via one uint4 of halves)

// Prep-kernel grid decomposition (transpose tiles are 64 rows x 128 cols)
#define T1_BLOCKS ((FDIM / 128) * (DDIM / 64))  // 1536 up_decoder tiles
#define T2_BLOCKS ((FDIM / 128) * (BS / 64))    // 2048 up_facts tiles
#define RP_BLOCKS (((FDIM + 1) + 255) / 256)    // 65 rowptr blocks

// Static device scratch (no allocations allowed in kernel_launch)
__device__ __half g_udT[(size_t)FDIM * DDIM];    // up_decoder transposed: [F, D], fp16
__device__ __half g_ufT[(size_t)FDIM * BS];      // up_facts transposed:   [F, BS], fp16
__device__ float  g_values[MCON];                // per-connection value (fp32)
__device__ int    g_rowptr[FDIM + 1];            // CSR row pointers over sorted i

// ---------------------------------------------------------------------------
// Transpose tile helper: 64 src rows x 128 src cols, fp32 -> fp16.
// Loads: float4 per lane (128B in flight per thread = 4x MLP vs scalar).
// Smem stores are scalar (stride-129 rows are NOT 16B aligned — float4 STS
// faults; scalar STS is the fix, smem store conflicts are cheap).
// Stores to gmem: half2 per lane -> full-width 128B transactions.
// Requires R % 64 == 0, C % 128 == 0 (true for all uses).
// ---------------------------------------------------------------------------
__device__ __forceinline__ void transpose_tile_f2h(const float* __restrict__ src,
                                                   __half* __restrict__ dst,
                                                   int R, int C, int bx, int by,
                                                   int x, int y) {
    __shared__ float tile[64][129];   // pad 1 float: 2-way on transposed reads
    const int c0 = bx * 128;
    const int r0 = by * 64;

    const float4* src4 = reinterpret_cast<const float4*>(src);
    const int c4 = C >> 2;
#pragma unroll
    for (int k = 0; k < 64; k += 8) {
        int row = y + k;
        float4 v = src4[(size_t)(r0 + row) * c4 + (c0 >> 2) + x];
        tile[row][4 * x + 0] = v.x;
        tile[row][4 * x + 1] = v.y;
        tile[row][4 * x + 2] = v.z;
        tile[row][4 * x + 3] = v.w;
    }
    __syncthreads();

    __half2* dst2 = reinterpret_cast<__half2*>(dst);
    const int rhalf = R >> 1;
#pragma unroll
    for (int dr = 0; dr < 128; dr += 8) {
        int row = dr + y;             // src col / dst row within tile
        __half2 v = __floats2half2_rn(tile[2 * x][row], tile[2 * x + 1][row]);
        dst2[(size_t)(c0 + row) * rhalf + (r0 >> 1) + x] = v;
    }
}

// ---------------------------------------------------------------------------
// Merged prep kernel: both transposes + rowptr, branched on block range.
// ---------------------------------------------------------------------------
__global__ void prep_kernel(const float* __restrict__ up_decoder,
                            const float* __restrict__ up_facts,
                            const int* __restrict__ i_indices,
                            __half* __restrict__ udT,
                            __half* __restrict__ ufT) {
    const int b = blockIdx.x;
    const int x = threadIdx.x & 31;
    const int y = threadIdx.x >> 5;

    if (b < T1_BLOCKS) {
        // up_decoder [DDIM, FDIM] -> udT [FDIM, DDIM]
        int bx = b % (FDIM / 128);
        int by = b / (FDIM / 128);
        transpose_tile_f2h(up_decoder, udT, DDIM, FDIM, bx, by, x, y);
    } else if (b < T1_BLOCKS + T2_BLOCKS) {
        // up_facts [BS, FDIM] -> ufT [FDIM, BS]
        int bb = b - T1_BLOCKS;
        int bx = bb % (FDIM / 128);
        int by = bb / (FDIM / 128);
        transpose_tile_f2h(up_facts, ufT, BS, FDIM, bx, by, x, y);
    } else {
        // rowptr: g_rowptr[f] = lower_bound(i_indices, f)
        int f = (b - T1_BLOCKS - T2_BLOCKS) * 256 + threadIdx.x;
        if (f > FDIM) return;
        int lo = 0, hi = MCON;
        while (lo < hi) {
            int mid = (lo + hi) >> 1;
            if (i_indices[mid] < f) lo = mid + 1;
            else hi = mid;
        }
        g_rowptr[f] = lo;
    }
}

// ---------------------------------------------------------------------------
// Dot helper: 24-elem partial dot of fp32 E regs vs fp16 U row.
// ---------------------------------------------------------------------------
__device__ __forceinline__ float dot24(const float4* ea, const float4* eb,
                                       const uint4* __restrict__ U, int lane) {
    float s = 0.0f;
#pragma unroll
    for (int k = 0; k < 3; k++) {
        uint4 u = U[k * 32 + lane];
        float2 f0 = __half22float2(*reinterpret_cast<const __half2*>(&u.x));
        float2 f1 = __half22float2(*reinterpret_cast<const __half2*>(&u.y));
        float2 f2 = __half22float2(*reinterpret_cast<const __half2*>(&u.z));
        float2 f3 = __half22float2(*reinterpret_cast<const __half2*>(&u.w));
        s += ea[k].x * f0.x + ea[k].y * f0.y + ea[k].z * f1.x + ea[k].w * f1.y;
        s += eb[k].x * f2.x + eb[k].y * f2.y + eb[k].z * f3.x + eb[k].w * f3.y;
    }
    return s;
}

// ---------------------------------------------------------------------------
// SDDMM values: TWO warps per i-row (even/odd m split), two m's per
// iteration with a merged butterfly reduce (6 shuffles per 2 m's).
// ---------------------------------------------------------------------------
__global__ void values_kernel(const float* __restrict__ down_encoder,
                              const int* __restrict__ j_indices) {
    int gwarp = (blockIdx.x * blockDim.x + threadIdx.x) >> 5;
    int lane = threadIdx.x & 31;
    if (gwarp >= FDIM * 2) return;
    const int i      = gwarp >> 1;
    const int parity = gwarp & 1;

    // Load E[i] in pairs of float4 matching the uint4-of-8-halves layout.
    const float4* E4 = reinterpret_cast<const float4*>(down_encoder + (size_t)i * DDIM);
    float4 ea[3], eb[3];
#pragma unroll
    for (int k = 0; k < 3; k++) {
        int base = 2 * (k * 32 + lane);
        ea[k] = E4[base];
        eb[k] = E4[base + 1];
    }

    int m1 = g_rowptr[i + 1];
    int m = g_rowptr[i] + parity;

    // Paired iterations: this warp's m and m+2, merged reduction.
    for (; m + 2 < m1; m += 4) {
        int j0 = __ldg(&j_indices[m]);
        int j1 = __ldg(&j_indices[m + 2]);
        const uint4* U0 = reinterpret_cast<const uint4*>(g_udT + (size_t)j0 * DDIM);
        const uint4* U1 = reinterpret_cast<const uint4*>(g_udT + (size_t)j1 * DDIM);
        float s0 = dot24(ea, eb, U0, lane);
        float s1 = dot24(ea, eb, U1, lane);
        // Merge: fold 16-halves, select per half, then shared 4-step butterfly.
        s0 += __shfl_xor_sync(0xffffffffu, s0, 16);
        s1 += __shfl_xor_sync(0xffffffffu, s1, 16);
        float sm = (lane & 16) ? s1 : s0;
#pragma unroll
        for (int off = 8; off; off >>= 1)
            sm += __shfl_xor_sync(0xffffffffu, sm, off);
        if (lane == 0)  g_values[m]     = sm;
        if (lane == 16) g_values[m + 2] = sm;
    }
    // Tail: single m's.
    for (; m < m1; m += 2) {
        int j = __ldg(&j_indices[m]);
        const uint4* U = reinterpret_cast<const uint4*>(g_udT + (size_t)j * DDIM);
        float s = dot24(ea, eb, U, lane);
#pragma unroll
        for (int off = 16; off; off >>= 1)
            s += __shfl_xor_sync(0xffffffffu, s, off);
        if (lane == 0) g_values[m] = s;
    }
}

// ---------------------------------------------------------------------------
// Fused SpMM + output transpose, fp16 activations, fp32 accumulate.
// Block computes [TI=32 i-rows] x [TT=256 tokens]. Warp handles 4 i-rows;
// lane owns 8 consecutive tokens (one uint4 of halves per m).
// Staged in smem, written to out[token][i] as coalesced 128B rows.
// ---------------------------------------------------------------------------
__global__ void spmm_fused_kernel(const int* __restrict__ j_indices,
                                  float* __restrict__ out) {
    __shared__ float tile[TI][TT + 1];   // pad 1: conflict-free column reads

    const int i_base = blockIdx.x * TI;
    const int tok0   = blockIdx.y * TT;
    const int warp   = threadIdx.x >> 5;
    const int lane   = threadIdx.x & 31;

    const uint4* uf = reinterpret_cast<const uint4*>(g_ufT);
    const int tcol = (tok0 >> 3) + lane;   // uint4 index into a ufT row (BS/8 per row)

    for (int ii = warp; ii < TI; ii += 8) {
        const int i = i_base + ii;
        int m0 = g_rowptr[i];
        int m1 = g_rowptr[i + 1];

        float acc[8];
#pragma unroll
        for (int t = 0; t < 8; t++) acc[t] = 0.0f;

        int m = m0;
        for (; m + 1 < m1; m += 2) {
            float v0 = g_values[m];
            float v1 = g_values[m + 1];
            int j0 = __ldg(&j_indices[m]);
            int j1 = __ldg(&j_indices[m + 1]);
            uint4 u0 = uf[(size_t)j0 * (BS / 8) + tcol];
            uint4 u1 = uf[(size_t)j1 * (BS / 8) + tcol];
            {
                float2 f0 = __half22float2(*reinterpret_cast<__half2*>(&u0.x));
                float2 f1 = __half22float2(*reinterpret_cast<__half2*>(&u0.y));
                float2 f2 = __half22float2(*reinterpret_cast<__half2*>(&u0.z));
                float2 f3 = __half22float2(*reinterpret_cast<__half2*>(&u0.w));
                acc[0] += v0 * f0.x; acc[1] += v0 * f0.y;
                acc[2] += v0 * f1.x; acc[3] += v0 * f1.y;
                acc[4] += v0 * f2.x; acc[5] += v0 * f2.y;
                acc[6] += v0 * f3.x; acc[7] += v0 * f3.y;
            }
            {
                float2 f0 = __half22float2(*reinterpret_cast<__half2*>(&u1.x));
                float2 f1 = __half22float2(*reinterpret_cast<__half2*>(&u1.y));
                float2 f2 = __half22float2(*reinterpret_cast<__half2*>(&u1.z));
                float2 f3 = __half22float2(*reinterpret_cast<__half2*>(&u1.w));
                acc[0] += v1 * f0.x; acc[1] += v1 * f0.y;
                acc[2] += v1 * f1.x; acc[3] += v1 * f1.y;
                acc[4] += v1 * f2.x; acc[5] += v1 * f2.y;
                acc[6] += v1 * f3.x; acc[7] += v1 * f3.y;
            }
        }
        for (; m < m1; m++) {
            float v = g_values[m];
            int j = __ldg(&j_indices[m]);
            uint4 u = uf[(size_t)j * (BS / 8) + tcol];
            float2 f0 = __half22float2(*reinterpret_cast<__half2*>(&u.x));
            float2 f1 = __half22float2(*reinterpret_cast<__half2*>(&u.y));
            float2 f2 = __half22float2(*reinterpret_cast<__half2*>(&u.z));
            float2 f3 = __half22float2(*reinterpret_cast<__half2*>(&u.w));
            acc[0] += v * f0.x; acc[1] += v * f0.y;
            acc[2] += v * f1.x; acc[3] += v * f1.y;
            acc[4] += v * f2.x; acc[5] += v * f2.y;
            acc[6] += v * f3.x; acc[7] += v * f3.y;
        }

#pragma unroll
        for (int t = 0; t < 8; t++)
            tile[ii][lane * 8 + t] = acc[t];
    }
    __syncthreads();

    // Write out: warp writes one token row per iter (32 consecutive i's = 128B)
    for (int t = warp; t < TT; t += 8) {
        out[(size_t)(tok0 + t) * FDIM + i_base + lane] = tile[lane][t];
    }
}

// ---------------------------------------------------------------------------
// Launch sequence: prep (transposes + rowptr) -> values -> spmm
// ---------------------------------------------------------------------------
extern "C" void kernel_launch(void* const* d_in, const int* in_sizes, int n_in,
                              void* d_out, int out_size) {
    const float* up_facts     = (const float*)d_in[0];   // [B, S, F]
    const float* down_encoder = (const float*)d_in[1];   // [F, D]
    const float* up_decoder   = (const float*)d_in[2];   // [D, F]
    const int*   i_indices    = (const int*)d_in[3];     // [M], sorted, int32
    const int*   j_indices    = (const int*)d_in[4];     // [M], int32
    float*       out          = (float*)d_out;           // [B, S, F]

    __half* udT; cudaGetSymbolAddress((void**)&udT, g_udT);
    __half* ufT; cudaGetSymbolAddress((void**)&ufT, g_ufT);

    // 1) Prep: transpose up_decoder + transpose up_facts + rowptr (one launch)
    {
        int blocks = T1_BLOCKS + T2_BLOCKS + RP_BLOCKS;
        prep_kernel<<<blocks, 256>>>(up_decoder, up_facts, i_indices, udT, ufT);
    }
    // 2) SDDMM values (2 warps per i, paired reduce)
    {
        int threads = 256;
        long long total_threads = (long long)FDIM * 2 * 32;
        int blocks = (int)((total_threads + threads - 1) / threads);
        values_kernel<<<blocks, threads>>>(down_encoder, j_indices);
    }
    // 3) Fused SpMM + output transpose
    {
        dim3 grid(FDIM / TI, BS / TT);
        spmm_fused_kernel<<<grid, 256>>>(j_indices, out);
    }
}

// round 10
// speedup vs baseline: 1.0698x; 1.0698x over previous
#include <cuda_runtime.h>
#include <cuda_fp16.h>
#include <cstdint>

// Problem constants (fixed by the dataset)
#define BATCH 2
#define SEQ   512
#define BS    (BATCH * SEQ)      // 1024 tokens
#define FDIM  16384              // n_features
#define DDIM  768                // d_model
#define MCON  262144             // n_connections

// SpMM tile
#define TI 32    // i rows per block
#define TT 256   // tokens per block (lane owns 8 via one uint4 of halves)

// Prep-kernel grid decomposition (transpose tiles are 64 rows x 32 cols)
#define T1_BLOCKS ((FDIM / 32) * (DDIM / 64))   // 6144 up_decoder tiles
#define T2_BLOCKS ((FDIM / 32) * (BS / 64))     // 8192 up_facts tiles
#define RP_BLOCKS (((FDIM + 1) + 255) / 256)    // 65 rowptr blocks

// Static device scratch (no allocations allowed in kernel_launch)
__device__ __half g_udT[(size_t)FDIM * DDIM];    // up_decoder transposed: [F, D], fp16
__device__ __half g_ufT[(size_t)FDIM * BS];      // up_facts transposed:   [F, BS], fp16
__device__ float  g_values[MCON];                // per-connection value (fp32)
__device__ int    g_rowptr[FDIM + 1];            // CSR row pointers over sorted i

// ---------------------------------------------------------------------------
// Transpose device helper (R7 version — empirically the best): 64 src rows x
// 32 src cols tile, fp32 -> fp16, half2-vectorized gmem stores.
// ---------------------------------------------------------------------------
__device__ __forceinline__ void transpose_tile_f2h(const float* __restrict__ src,
                                                   __half* __restrict__ dst,
                                                   int R, int C, int bx, int by,
                                                   int x, int y) {
    __shared__ float tile[64][33];
    const int c0 = bx * 32;
    const int r0 = by * 64;

#pragma unroll
    for (int k = 0; k < 64; k += 8) {
        tile[y + k][x] = src[(size_t)(r0 + y + k) * C + c0 + x];
    }
    __syncthreads();

    __half2* dst2 = reinterpret_cast<__half2*>(dst);
    const int rhalf = R >> 1;
#pragma unroll
    for (int dr = 0; dr < 32; dr += 8) {
        int row = dr + y;             // src col / dst row within tile
        __half2 v = __floats2half2_rn(tile[2 * x][row], tile[2 * x + 1][row]);
        dst2[(size_t)(c0 + row) * rhalf + (r0 >> 1) + x] = v;
    }
}

// ---------------------------------------------------------------------------
// Merged prep kernel: both transposes + rowptr, branched on block range.
// Fires the PDL trigger immediately: the dependent kernel may begin its
// launch ramp + independent prologue while we run.
// ---------------------------------------------------------------------------
__global__ void prep_kernel(const float* __restrict__ up_decoder,
                            const float* __restrict__ up_facts,
                            const int* __restrict__ i_indices,
                            __half* __restrict__ udT,
                            __half* __restrict__ ufT) {
    cudaTriggerProgrammaticLaunchCompletion();
    const int b = blockIdx.x;
    const int x = threadIdx.x & 31;
    const int y = threadIdx.x >> 5;

    if (b < T1_BLOCKS) {
        // up_decoder [DDIM, FDIM] -> udT [FDIM, DDIM]
        int bx = b % (FDIM / 32);
        int by = b / (FDIM / 32);
        transpose_tile_f2h(up_decoder, udT, DDIM, FDIM, bx, by, x, y);
    } else if (b < T1_BLOCKS + T2_BLOCKS) {
        // up_facts [BS, FDIM] -> ufT [FDIM, BS]
        int bb = b - T1_BLOCKS;
        int bx = bb % (FDIM / 32);
        int by = bb / (FDIM / 32);
        transpose_tile_f2h(up_facts, ufT, BS, FDIM, bx, by, x, y);
    } else {
        // rowptr: g_rowptr[f] = lower_bound(i_indices, f)
        int f = (b - T1_BLOCKS - T2_BLOCKS) * 256 + threadIdx.x;
        if (f > FDIM) return;
        int lo = 0, hi = MCON;
        while (lo < hi) {
            int mid = (lo + hi) >> 1;
            if (i_indices[mid] < f) lo = mid + 1;
            else hi = mid;
        }
        g_rowptr[f] = lo;
    }
}

// ---------------------------------------------------------------------------
// SDDMM values: TWO warps per i-row (even/odd m split) for latency hiding.
// E[i] held fp32 in registers, layout-matched to the fp16 U row loads.
// PDL: E loads (independent of prep) run before the grid sync.
// ---------------------------------------------------------------------------
__global__ void values_kernel(const float* __restrict__ down_encoder,
                              const int* __restrict__ j_indices) {
    cudaTriggerProgrammaticLaunchCompletion();
    int gwarp = (blockIdx.x * blockDim.x + threadIdx.x) >> 5;
    int lane = threadIdx.x & 31;
    if (gwarp >= FDIM * 2) {
        cudaGridDependencySynchronize();
        return;
    }
    const int i      = gwarp >> 1;
    const int parity = gwarp & 1;

    // Prologue independent of prep: load E[i] (pairs of float4 matching the
    // uint4-of-8-halves layout of udT rows).
    const float4* E4 = reinterpret_cast<const float4*>(down_encoder + (size_t)i * DDIM);
    float4 ea[3], eb[3];
#pragma unroll
    for (int k = 0; k < 3; k++) {
        int base = 2 * (k * 32 + lane);
        ea[k] = E4[base];
        eb[k] = E4[base + 1];
    }

    // Wait for prep (udT + rowptr) to be complete and visible.
    cudaGridDependencySynchronize();

    int m1 = g_rowptr[i + 1];
    for (int m = g_rowptr[i] + parity; m < m1; m += 2) {
        int j = __ldg(&j_indices[m]);
        const uint4* U = reinterpret_cast<const uint4*>(g_udT + (size_t)j * DDIM);
        float s = 0.0f;
#pragma unroll
        for (int k = 0; k < 3; k++) {
            uint4 u = U[k * 32 + lane];
            float2 f0 = __half22float2(*reinterpret_cast<__half2*>(&u.x));
            float2 f1 = __half22float2(*reinterpret_cast<__half2*>(&u.y));
            float2 f2 = __half22float2(*reinterpret_cast<__half2*>(&u.z));
            float2 f3 = __half22float2(*reinterpret_cast<__half2*>(&u.w));
            s += ea[k].x * f0.x + ea[k].y * f0.y + ea[k].z * f1.x + ea[k].w * f1.y;
            s += eb[k].x * f2.x + eb[k].y * f2.y + eb[k].z * f3.x + eb[k].w * f3.y;
        }
#pragma unroll
        for (int off = 16; off; off >>= 1)
            s += __shfl_xor_sync(0xffffffffu, s, off);
        if (lane == 0) g_values[m] = s;
    }
}

// ---------------------------------------------------------------------------
// Fused SpMM + output transpose, fp16 activations, fp32 accumulate.
// Block computes [TI=32 i-rows] x [TT=256 tokens]. Warp handles 4 i-rows;
// lane owns 8 consecutive tokens (one uint4 of halves per m).
// Staged in smem, written to out[token][i] as coalesced 128B rows.
// ---------------------------------------------------------------------------
__global__ void spmm_fused_kernel(const int* __restrict__ j_indices,
                                  float* __restrict__ out) {
    cudaGridDependencySynchronize();

    __shared__ float tile[TI][TT + 1];   // pad 1: conflict-free column reads

    const int i_base = blockIdx.x * TI;
    const int tok0   = blockIdx.y * TT;
    const int warp   = threadIdx.x >> 5;
    const int lane   = threadIdx.x & 31;

    const uint4* uf = reinterpret_cast<const uint4*>(g_ufT);
    const int tcol = (tok0 >> 3) + lane;   // uint4 index into a ufT row (BS/8 per row)

    for (int ii = warp; ii < TI; ii += 8) {
        const int i = i_base + ii;
        int m0 = g_rowptr[i];
        int m1 = g_rowptr[i + 1];

        float acc[8];
#pragma unroll
        for (int t = 0; t < 8; t++) acc[t] = 0.0f;

        int m = m0;
        for (; m + 1 < m1; m += 2) {
            float v0 = g_values[m];
            float v1 = g_values[m + 1];
            int j0 = __ldg(&j_indices[m]);
            int j1 = __ldg(&j_indices[m + 1]);
            uint4 u0 = uf[(size_t)j0 * (BS / 8) + tcol];
            uint4 u1 = uf[(size_t)j1 * (BS / 8) + tcol];
            {
                float2 f0 = __half22float2(*reinterpret_cast<__half2*>(&u0.x));
                float2 f1 = __half22float2(*reinterpret_cast<__half2*>(&u0.y));
                float2 f2 = __half22float2(*reinterpret_cast<__half2*>(&u0.z));
                float2 f3 = __half22float2(*reinterpret_cast<__half2*>(&u0.w));
                acc[0] += v0 * f0.x; acc[1] += v0 * f0.y;
                acc[2] += v0 * f1.x; acc[3] += v0 * f1.y;
                acc[4] += v0 * f2.x; acc[5] += v0 * f2.y;
                acc[6] += v0 * f3.x; acc[7] += v0 * f3.y;
            }
            {
                float2 f0 = __half22float2(*reinterpret_cast<__half2*>(&u1.x));
                float2 f1 = __half22float2(*reinterpret_cast<__half2*>(&u1.y));
                float2 f2 = __half22float2(*reinterpret_cast<__half2*>(&u1.z));
                float2 f3 = __half22float2(*reinterpret_cast<__half2*>(&u1.w));
                acc[0] += v1 * f0.x; acc[1] += v1 * f0.y;
                acc[2] += v1 * f1.x; acc[3] += v1 * f1.y;
                acc[4] += v1 * f2.x; acc[5] += v1 * f2.y;
                acc[6] += v1 * f3.x; acc[7] += v1 * f3.y;
            }
        }
        for (; m < m1; m++) {
            float v = g_values[m];
            int j = __ldg(&j_indices[m]);
            uint4 u = uf[(size_t)j * (BS / 8) + tcol];
            float2 f0 = __half22float2(*reinterpret_cast<__half2*>(&u.x));
            float2 f1 = __half22float2(*reinterpret_cast<__half2*>(&u.y));
            float2 f2 = __half22float2(*reinterpret_cast<__half2*>(&u.z));
            float2 f3 = __half22float2(*reinterpret_cast<__half2*>(&u.w));
            acc[0] += v * f0.x; acc[1] += v * f0.y;
            acc[2] += v * f1.x; acc[3] += v * f1.y;
            acc[4] += v * f2.x; acc[5] += v * f2.y;
            acc[6] += v * f3.x; acc[7] += v * f3.y;
        }

#pragma unroll
        for (int t = 0; t < 8; t++)
            tile[ii][lane * 8 + t] = acc[t];
    }
    __syncthreads();

    // Write out: warp writes one token row per iter (32 consecutive i's = 128B)
    for (int t = warp; t < TT; t += 8) {
        out[(size_t)(tok0 + t) * FDIM + i_base + lane] = tile[lane][t];
    }
}

// ---------------------------------------------------------------------------
// Launch sequence with PDL overlap: prep -> values -> spmm
// ---------------------------------------------------------------------------
extern "C" void kernel_launch(void* const* d_in, const int* in_sizes, int n_in,
                              void* d_out, int out_size) {
    const float* up_facts     = (const float*)d_in[0];   // [B, S, F]
    const float* down_encoder = (const float*)d_in[1];   // [F, D]
    const float* up_decoder   = (const float*)d_in[2];   // [D, F]
    const int*   i_indices    = (const int*)d_in[3];     // [M], sorted, int32
    const int*   j_indices    = (const int*)d_in[4];     // [M], int32
    float*       out          = (float*)d_out;           // [B, S, F]

    __half* udT; cudaGetSymbolAddress((void**)&udT, g_udT);
    __half* ufT; cudaGetSymbolAddress((void**)&ufT, g_ufT);

    // 1) Prep: transpose up_decoder + transpose up_facts + rowptr (one launch)
    {
        int blocks = T1_BLOCKS + T2_BLOCKS + RP_BLOCKS;
        prep_kernel<<<blocks, 256>>>(up_decoder, up_facts, i_indices, udT, ufT);
    }
    // 2) SDDMM values (2 warps per i) — PDL-overlapped with prep's tail
    {
        int threads = 256;
        long long total_threads = (long long)FDIM * 2 * 32;
        int blocks = (int)((total_threads + threads - 1) / threads);

        cudaLaunchConfig_t cfg = {};
        cfg.gridDim  = dim3((unsigned)blocks);
        cfg.blockDim = dim3((unsigned)threads);
        cfg.dynamicSmemBytes = 0;
        cfg.stream = 0;
        cudaLaunchAttribute attr[1];
        attr[0].id = cudaLaunchAttributeProgrammaticStreamSerialization;
        attr[0].val.programmaticStreamSerializationAllowed = 1;
        cfg.attrs = attr;
        cfg.numAttrs = 1;
        cudaLaunchKernelEx(&cfg, values_kernel, down_encoder, j_indices);
    }
    // 3) Fused SpMM + output transpose — PDL-overlapped with values' tail
    {
        cudaLaunchConfig_t cfg = {};
        cfg.gridDim  = dim3(FDIM / TI, BS / TT);
        cfg.blockDim = dim3(256);
        cfg.dynamicSmemBytes = 0;
        cfg.stream = 0;
        cudaLaunchAttribute attr[1];
        attr[0].id = cudaLaunchAttributeProgrammaticStreamSerialization;
        attr[0].val.programmaticStreamSerializationAllowed = 1;
        cfg.attrs = attr;
        cfg.numAttrs = 1;
        cudaLaunchKernelEx(&cfg, spmm_fused_kernel, j_indices, out);
    }
}